// round 14
// baseline (speedup 1.0000x reference)
#include <cuda_runtime.h>

#define B_    8
#define C_    20
#define H_    512
#define W_    512
#define SH_   32
#define SW_   32
#define S_    1024
#define CELL_ 16
#define HW_   (H_*W_)
#define HW4   (HW_/4)        // ulonglong2 (16B) chunks per channel plane
#define W4    (W_/4)         // 16B chunks per image row
#define PSTR  260
#define EPSV  1e-8f

typedef unsigned long long u64;

// Packed fp32x2 helpers (SASS FFMA2 — PTX-only)
__device__ __forceinline__ u64 pkdup(float s) {
    u64 r; asm("mov.b64 %0,{%1,%1};" : "=l"(r) : "f"(s)); return r;
}
__device__ __forceinline__ void upk2(u64 v, float& lo, float& hi) {
    asm("mov.b64 {%0,%1},%2;" : "=f"(lo), "=f"(hi) : "l"(v));
}
__device__ __forceinline__ u64 fma2(u64 a, u64 b, u64 c) {
    u64 d; asm("fma.rn.f32x2 %0,%1,%2,%3;" : "=l"(d) : "l"(a), "l"(b), "l"(c));
    return d;
}

__device__ float g_seeds[B_][S_][C_];          // iteration-0 seeds (means)
__device__ float g_numerB[3][B_][S_][C_];      // per-iteration accumulators
__device__ float g_denomB[3][B_][S_];

__constant__ int c_dy[9] = {-1,-1,-1, 0,0,0, 1,1,1};
__constant__ int c_dx[9] = {-1, 0, 1,-1,0,1,-1,0,1};

// ---------------------------------------------------------------------------
// K0: seed init = 16x16 mean pool per (b, cell, c); zero ALL 3 accumulator
// buffers (seed division is fused into k_main's seed loader).
// ---------------------------------------------------------------------------
__global__ void __launch_bounds__(256) k_init(const float* __restrict__ x)
{
    __shared__ __align__(16) float sX[C_][PSTR];
    const int b  = blockIdx.z, cy = blockIdx.y, cx = blockIdx.x;
    const int tid = threadIdx.x;
    const int ty = tid >> 4, tx = tid & 15;
    const int sidx = cy * SW_ + cx;

    if (tid < 63) {
        const int buf = tid / 21, c = tid % 21;
        if (c < 20) g_numerB[buf][b][sidx][c] = 0.f;
        else        g_denomB[buf][b][sidx]    = 0.f;
    }

    const float* xp = x + (size_t)b * C_ * HW_
                        + (size_t)(cy * CELL_ + ty) * W_ + (cx * CELL_ + tx);
#pragma unroll
    for (int c = 0; c < C_; c++) sX[c][tid] = xp[(size_t)c * HW_];
    __syncthreads();

    if (tid < C_) {
        const float4* r = (const float4*)sX[tid];
        float a0 = 0.f, a1 = 0.f, a2 = 0.f, a3 = 0.f;
#pragma unroll
        for (int p = 0; p < 64; p++) {
            float4 v = r[p];
            a0 += v.x; a1 += v.y; a2 += v.z; a3 += v.w;
        }
        g_seeds[b][sidx][tid] = ((a0 + a1) + (a2 + a3)) * (1.f / 256.f);
    }
}

// ---------------------------------------------------------------------------
// Main kernel: one CTA = ONE WARP = one (b, cell). 32 threads, thread = 8
// adjacent pixels (half row). Seed-broadcast LDS bytes scale with #threads:
// 46KB -> 23KB/CTA. logit[o] = 2*x.s_o - |s_o|^2.
//
// Accumulate iters:
//  - denominators: butterfly over the single warp, lane 0 atomics
//  - numerator GEMM out[o][c] = Sigma_p Q[o][p]*X[c][p]: 32 threads =
//    (ALL 9 o x 5 c) tiles x 4 cgr x 8 K-slices -> X re-read 1x (was 3x).
//    Partials staged in sPart[28][49] (49: odd stride -> conflict-free).
// ---------------------------------------------------------------------------
template<int SRC, bool FINAL>
__global__ void __launch_bounds__(32, 12) k_main(const float* __restrict__ x,
                                                 float* __restrict__ out)
{
    __shared__ float sS[9][20];                    // 2*seed (rows 80B, 16B-aligned)
    __shared__ float sD0[9];                       // |seed|^2
    __shared__ int   sIdx[9];                      // clipped global seed index
    __shared__ float sPart[28][49];                // K-slice partials (45 used)
    __shared__ __align__(16) float sQ[9][PSTR];    // staged Q (260 = 65 chunks)

    const int b  = blockIdx.z, cy = blockIdx.y, cx = blockIdx.x;
    const int tid = threadIdx.x;

    // Thread's 8 pixels: half row of the cell
    const int ty  = tid >> 1;
    const int tx0 = (tid & 1) * 8;
    const float* xp = x + (size_t)b * C_ * HW_
                        + (size_t)(cy * CELL_ + ty) * W_ + (cx * CELL_ + tx0);
    const ulonglong2* xq = (const ulonglong2*)xp;

    // PREFETCH channel pair g=0 before the seed barrier
    ulonglong2 pa0 = xq[0],   pa1 = xq[1];
    ulonglong2 pb0 = xq[HW4], pb1 = xq[HW4 + 1];

    // Seed tile (pre-doubled) + neighbor indices, strided over 32 threads
    for (int t = tid; t < 180; t += 32) {
        const int o = t / 20, c = t - o * 20;
        int iy = cy + c_dy[o]; iy = iy < 0 ? 0 : (iy > SH_ - 1 ? SH_ - 1 : iy);
        int ix = cx + c_dx[o]; ix = ix < 0 ? 0 : (ix > SW_ - 1 ? SW_ - 1 : ix);
        const int sidx = iy * SW_ + ix;
        if (c == 0) sIdx[o] = sidx;
        float sv;
        if (SRC == 0) {
            sv = g_seeds[b][sidx][c];
        } else {
            sv = g_numerB[SRC - 1][b][sidx][c]
               / (g_denomB[SRC - 1][b][sidx] + EPSV);
        }
        sS[o][c] = 2.f * sv;
    }
    __syncthreads();

    if (tid < 9) {
        float a = 0.f;
#pragma unroll
        for (int c = 0; c < C_; c++) a += sS[tid][c] * sS[tid][c];
        sD0[tid] = 0.25f * a;   // sS holds 2s
    }

    // Logits, packed: L[o][q] = px pair (2q, 2q+1); stream 2 channels/group
    u64 L[9][4];
#pragma unroll
    for (int o = 0; o < 9; o++)
#pragma unroll
        for (int q = 0; q < 4; q++) L[o][q] = 0ull;

#pragma unroll
    for (int g = 0; g < 10; g++) {
        ulonglong2 xa0, xa1, xb0, xb1;
        if (g == 0) { xa0 = pa0; xa1 = pa1; xb0 = pb0; xb1 = pb1; }
        else {
            xa0 = xq[(size_t)(2 * g) * HW4];
            xa1 = xq[(size_t)(2 * g) * HW4 + 1];
            xb0 = xq[(size_t)(2 * g + 1) * HW4];
            xb1 = xq[(size_t)(2 * g + 1) * HW4 + 1];
        }
#pragma unroll
        for (int o = 0; o < 9; o++) {
            const float2 s2 = *(const float2*)&sS[o][2 * g];
            const u64 b0 = pkdup(s2.x), b1 = pkdup(s2.y);
            L[o][0] = fma2(xa0.x, b0, L[o][0]);
            L[o][1] = fma2(xa0.y, b0, L[o][1]);
            L[o][2] = fma2(xa1.x, b0, L[o][2]);
            L[o][3] = fma2(xa1.y, b0, L[o][3]);
            L[o][0] = fma2(xb0.x, b1, L[o][0]);
            L[o][1] = fma2(xb0.y, b1, L[o][1]);
            L[o][2] = fma2(xb1.x, b1, L[o][2]);
            L[o][3] = fma2(xb1.y, b1, L[o][3]);
        }
    }
    __syncthreads();   // sD0 ready

    // Unpack, subtract |s|^2, softmax over o per pixel (8 pixels)
    float Lf[9][8];
#pragma unroll
    for (int o = 0; o < 9; o++) {
        upk2(L[o][0], Lf[o][0], Lf[o][1]);
        upk2(L[o][1], Lf[o][2], Lf[o][3]);
        upk2(L[o][2], Lf[o][4], Lf[o][5]);
        upk2(L[o][3], Lf[o][6], Lf[o][7]);
        const float d0 = sD0[o];
#pragma unroll
        for (int j = 0; j < 8; j++) Lf[o][j] -= d0;
    }
#pragma unroll
    for (int j = 0; j < 8; j++) {
        float m = Lf[0][j];
#pragma unroll
        for (int o = 1; o < 9; o++) m = fmaxf(m, Lf[o][j]);
        float sum = 0.f;
#pragma unroll
        for (int o = 0; o < 9; o++) { Lf[o][j] = __expf(Lf[o][j] - m); sum += Lf[o][j]; }
        const float inv = 1.f / sum;
#pragma unroll
        for (int o = 0; o < 9; o++) Lf[o][j] *= inv;
    }

    if constexpr (FINAL) {
        const int yy = cy * CELL_ + ty, xx = cx * CELL_ + tx0;
        float* op = out + (size_t)b * 9 * HW_ + (size_t)yy * W_ + xx;
#pragma unroll
        for (int o = 0; o < 9; o++) {
            *(float4*)(op + (size_t)o * HW_) =
                make_float4(Lf[o][0], Lf[o][1], Lf[o][2], Lf[o][3]);
            *(float4*)(op + (size_t)o * HW_ + 4) =
                make_float4(Lf[o][4], Lf[o][5], Lf[o][6], Lf[o][7]);
        }
        return;
    } else {

    // Stage Q (thread's 8 px = chunks 2*tid, 2*tid+1) + denom butterfly
    const int p0 = tid * 8;
    float qs[9];
#pragma unroll
    for (int o = 0; o < 9; o++) {
        *(float4*)&sQ[o][p0]     = make_float4(Lf[o][0], Lf[o][1], Lf[o][2], Lf[o][3]);
        *(float4*)&sQ[o][p0 + 4] = make_float4(Lf[o][4], Lf[o][5], Lf[o][6], Lf[o][7]);
        float a = 0.f;
#pragma unroll
        for (int j = 0; j < 8; j++) a += Lf[o][j];
        qs[o] = a;
    }
#pragma unroll
    for (int o = 0; o < 9; o++) {
#pragma unroll
        for (int d = 16; d >= 1; d >>= 1)
            qs[o] += __shfl_xor_sync(0xffffffffu, qs[o], d);
    }
    if (tid == 0) {
#pragma unroll
        for (int o = 0; o < 9; o++)
            atomicAdd(&g_denomB[SRC][b][sIdx[o]], qs[o]);
    }

    // GEMM setup: thread = (cgr = tid>>3 in 0..3, kq = tid&7 K-slice)
    const int cgr = tid >> 3, kq = tid & 7;
    const ulonglong2* xb = (const ulonglong2*)(x + (size_t)b * C_ * HW_
                                                 + (size_t)(cy * CELL_) * W_
                                                 + cx * CELL_);
    const int boff = (kq >> 2) * W4 + (kq & 3);   // chunk n=kq position
    const ulonglong2* px[5];
    ulonglong2 xpre[5];
#pragma unroll
    for (int jc = 0; jc < 5; jc++) {
        px[jc] = xb + (size_t)(5 * cgr + jc) * HW4 + boff;
        xpre[jc] = px[jc][0];     // i=0 prefetch (chunk n = kq)
    }
    __syncthreads();   // Q staged

    // Reduction GEMM: each thread does ALL 9 offsets x its 5 channels over
    // its 8 chunks (n = 8i + kq). X read once per chunk, held across o.
    u64 acc2[9][5];
#pragma unroll
    for (int jo = 0; jo < 9; jo++)
#pragma unroll
        for (int jc = 0; jc < 5; jc++) acc2[jo][jc] = 0ull;

#pragma unroll 2
    for (int i = 0; i < 8; i++) {
        const int n = 8 * i + kq;
        ulonglong2 xc[5];
#pragma unroll
        for (int jc = 0; jc < 5; jc++)
            xc[jc] = (i == 0) ? xpre[jc] : px[jc][(size_t)i * (2 * W4)];
#pragma unroll
        for (int jo = 0; jo < 9; jo++) {
            const ulonglong2 qv = ((const ulonglong2*)&sQ[jo][0])[n];
#pragma unroll
            for (int jc = 0; jc < 5; jc++) {
                acc2[jo][jc] = fma2(xc[jc].x, qv.x, acc2[jo][jc]);
                acc2[jo][jc] = fma2(xc[jc].y, qv.y, acc2[jo][jc]);
            }
        }
    }

    // Collapse packed lanes
    float accf[9][5];
#pragma unroll
    for (int jo = 0; jo < 9; jo++)
#pragma unroll
        for (int jc = 0; jc < 5; jc++) {
            float lo, hi; upk2(acc2[jo][jc], lo, hi);
            accf[jo][jc] = lo + hi;
        }

    // Combine the 8 K-slices: kq>0 stage, kq==0 accumulates + atomics
    if (kq > 0) {
        float* dst = sPart[cgr * 7 + (kq - 1)];
#pragma unroll
        for (int jo = 0; jo < 9; jo++)
#pragma unroll
            for (int jc = 0; jc < 5; jc++) dst[jo * 5 + jc] = accf[jo][jc];
    }
    __syncthreads();   // unconditional

    if (kq == 0) {
#pragma unroll
        for (int p = 0; p < 7; p++) {
            const float* src = sPart[cgr * 7 + p];
#pragma unroll
            for (int jo = 0; jo < 9; jo++)
#pragma unroll
                for (int jc = 0; jc < 5; jc++) accf[jo][jc] += src[jo * 5 + jc];
        }
#pragma unroll
        for (int jo = 0; jo < 9; jo++) {
            const int sidx = sIdx[jo];
#pragma unroll
            for (int jc = 0; jc < 5; jc++)
                atomicAdd(&g_numerB[SRC][b][sidx][5 * cgr + jc], accf[jo][jc]);
        }
    }
    }  // !FINAL
}

// ---------------------------------------------------------------------------
extern "C" void kernel_launch(void* const* d_in, const int* in_sizes, int n_in,
                              void* d_out, int out_size)
{
    const float* x = (const float*)d_in[0];
    float* out = (float*)d_out;

    dim3 grid(SW_, SH_, B_);

    k_init<<<grid, 256>>>(x);
    k_main<0, false><<<grid, 32>>>(x, nullptr);   // seeds=means  -> buf0
    k_main<1, false><<<grid, 32>>>(x, nullptr);   // seeds=buf0   -> buf1
    k_main<2, false><<<grid, 32>>>(x, nullptr);   // seeds=buf1   -> buf2
    k_main<3, true ><<<grid, 32>>>(x, out);       // seeds=buf2   -> output
}